// round 2
// baseline (speedup 1.0000x reference)
#include <cuda_runtime.h>
#include <cuda_bf16.h>
#include <math.h>

#define NN 50000
#define EE 800000
#define MT64 ((NN + 63) / 64)
#define NSZ (NN * 64)
#define NBLK_STATS 200
#define TSTR 4352            // 64 * 68 floats per smem tile
#define SLOT_SMEM (6 * TSTR * 4)

// ---------------- device scratch (no runtime allocation) ----------------
__device__ float g_stem[(size_t)NN * 192];
__device__ float g_x0[(size_t)NN * 64];
__device__ float g_a[(size_t)NN * 64];
__device__ float g_b[(size_t)NN * 64];
__device__ float g_cell0[(size_t)NN * 256];
__device__ float g_cell1[(size_t)NN * 256];
__device__ float g_sum[(size_t)5 * NSZ];
__device__ float g_nrm[(size_t)5 * NSZ];
__device__ float g_wcat[28 * 7 * 4096];
__device__ float g_wmix[14 * 8];
__device__ float g_stats[384];
__device__ float g_part[NBLK_STATS * 384];
__device__ float g_invdeg[NN];
__device__ float g_invsqrt[NN];
__device__ float g_ew[EE];
__device__ int g_deg[NN];
__device__ int g_cursor[NN];
__device__ int g_rowptr[NN + 1];
__device__ int g_eid[EE];
__device__ int g_srcs[EE];

// ---------------- CSR construction ----------------
__global__ void k_zero2(int* a, int* b) {
    int i = blockIdx.x * blockDim.x + threadIdx.x;
    if (i < NN) { a[i] = 0; b[i] = 0; }
}

__global__ void k_deg(const int* __restrict__ dst, int* __restrict__ deg) {
    int e = blockIdx.x * blockDim.x + threadIdx.x;
    if (e < EE) atomicAdd(&deg[dst[e]], 1);
}

__global__ void k_degfin(const int* __restrict__ deg, float* __restrict__ invdeg,
                         float* __restrict__ invsqrt) {
    int i = blockIdx.x * blockDim.x + threadIdx.x;
    if (i < NN) {
        float d = (float)max(deg[i], 1);
        invdeg[i] = 1.0f / d;
        invsqrt[i] = rsqrtf(d);
    }
}

__global__ void k_scan(const int* __restrict__ deg, int* __restrict__ rowptr) {
    __shared__ int buf[1024];
    __shared__ int carry_s;
    int tid = threadIdx.x;
    if (tid == 0) carry_s = 0;
    __syncthreads();
    int nch = (NN + 1023) / 1024;
    for (int c = 0; c < nch; c++) {
        int i = c * 1024 + tid;
        int v = (i < NN) ? deg[i] : 0;
        buf[tid] = v;
        __syncthreads();
        for (int off = 1; off < 1024; off <<= 1) {
            int t = (tid >= off) ? buf[tid - off] : 0;
            __syncthreads();
            buf[tid] += t;
            __syncthreads();
        }
        int excl = buf[tid] - v;
        int total = buf[1023];
        if (i < NN) rowptr[i] = carry_s + excl;
        __syncthreads();
        if (tid == 0) carry_s += total;
        __syncthreads();
    }
    if (tid == 0) rowptr[NN] = carry_s;
}

__global__ void k_scatter(const int* __restrict__ dst, const int* __restrict__ rowptr,
                          int* __restrict__ cursor, int* __restrict__ eid) {
    int e = blockIdx.x * blockDim.x + threadIdx.x;
    if (e < EE) {
        int d = dst[e];
        int pos = rowptr[d] + atomicAdd(&cursor[d], 1);
        eid[pos] = e;
    }
}

__global__ void k_sortfill(const int* __restrict__ rowptr, int* __restrict__ eid,
                           const int* __restrict__ src, const float* __restrict__ invsqrt,
                           int* __restrict__ srcs, float* __restrict__ ew) {
    int n = blockIdx.x * blockDim.x + threadIdx.x;
    if (n >= NN) return;
    int r0 = rowptr[n], r1 = rowptr[n + 1];
    for (int i = r0 + 1; i < r1; i++) {  // insertion sort by edge id -> determinism
        int key = eid[i];
        int j = i - 1;
        while (j >= r0 && eid[j] > key) { eid[j + 1] = eid[j]; j--; }
        eid[j + 1] = key;
    }
    float isd = invsqrt[n];
    for (int p = r0; p < r1; p++) {
        int e = eid[p];
        int s = src[e];
        srcs[p] = s;
        ew[p] = invsqrt[s] * isd;
    }
}

// ---------------- softmax + weight baking ----------------
__global__ void k_softmax(const float* __restrict__ alphas, float* __restrict__ wmix) {
    int r = threadIdx.x;
    if (r >= 14) return;
    float m = -1e30f;
    for (int o = 0; o < 8; o++) m = fmaxf(m, alphas[r * 8 + o]);
    float e[8], s = 0.f;
    for (int o = 0; o < 8; o++) { e[o] = expf(alphas[r * 8 + o] - m); s += e[o]; }
    float inv = 1.0f / s;
    for (int o = 0; o < 8; o++) wmix[r * 8 + o] = e[o] * inv;
}

__global__ void k_bake(const float* __restrict__ wmix,
                       const float* __restrict__ Wgcn, const float* __restrict__ Wss,
                       const float* __restrict__ Wsn, const float* __restrict__ Wgin,
                       const float* __restrict__ Wgc1, const float* __restrict__ Wgc2,
                       const float* __restrict__ Wmlp, const float* __restrict__ Wgcnii,
                       float* __restrict__ wcat) {
    int s = blockIdx.x;          // 0..27  (ci*14+ej)
    int ej = s % 14;
    const float* wv = wmix + ej * 8;
    size_t o = (size_t)s * 4096;
    size_t ob = (size_t)s * 7 * 4096;
    float w2 = wv[2], w3 = wv[3], w4 = wv[4], w5 = wv[5], w6 = wv[6], w7 = wv[7];
    for (int idx = threadIdx.x; idx < 4096; idx += blockDim.x) {
        // panel0 (A=h, linear): wv3*Wss + wv5*Wgc1 - wv5*Wgc2
        wcat[ob + 0 * 4096 + idx] = w3 * Wss[o + idx] + w5 * (Wgc1[o + idx] - Wgc2[o + idx]);
        // panel1 (A=s_mean, linear): wv3*Wsn
        wcat[ob + 1 * 4096 + idx] = w3 * Wsn[o + idx];
        // panel2 (A=h+s_sum, linear): wv5*Wgc2
        wcat[ob + 2 * 4096 + idx] = w5 * Wgc2[o + idx];
        // panel3 (A=s_norm, relu): wv2*Wgcn
        wcat[ob + 3 * 4096 + idx] = w2 * Wgcn[o + idx];
        // panel4 (A=h+s_sum, relu): wv4*Wgin
        wcat[ob + 4 * 4096 + idx] = w4 * Wgin[o + idx];
        // panel5 (A=h, relu): wv6*Wmlp
        wcat[ob + 5 * 4096 + idx] = w6 * Wmlp[o + idx];
        // panel6 (A=0.9*s_norm+0.1*x0, relu): wv7*Wgcnii
        wcat[ob + 6 * 4096 + idx] = w7 * Wgcnii[o + idx];
    }
}

// ---------------- generic tiled GEMM: C[M,Nout] = A[M,K]@B[K,Nout], raw out ----------------
__global__ __launch_bounds__(256) void k_gemm(const float* __restrict__ A, int lda,
                                              const float* __restrict__ B, int ldb,
                                              float* __restrict__ C, int K) {
    __shared__ float As[TSTR];
    __shared__ float Bs[TSTR];
    const int tid = threadIdx.x;
    const int m0 = blockIdx.x * 64;
    const int n0b = blockIdx.y * 64;
    const int tx = tid & 15, ty = tid >> 4;
    const int n0 = tx * 4, mm0 = ty * 4;
    float acc[16];
#pragma unroll
    for (int i = 0; i < 16; i++) acc[i] = 0.f;
    for (int kt = 0; kt < K; kt += 64) {
        __syncthreads();
#pragma unroll
        for (int i = 0; i < 16; i++) {
            int idx = tid + i * 256;
            int m = idx >> 6, k = idx & 63;
            int gm = m0 + m;
            As[k * 68 + m] = (gm < NN) ? A[(size_t)gm * lda + kt + k] : 0.f;
            Bs[(idx >> 6) * 68 + (idx & 63)] = B[(size_t)(kt + (idx >> 6)) * ldb + n0b + (idx & 63)];
        }
        __syncthreads();
#pragma unroll 16
        for (int k = 0; k < 64; k++) {
            float4 a4 = *(const float4*)&As[k * 68 + mm0];
            float4 b4 = *(const float4*)&Bs[k * 68 + n0];
            acc[0] += a4.x * b4.x; acc[1] += a4.x * b4.y; acc[2] += a4.x * b4.z; acc[3] += a4.x * b4.w;
            acc[4] += a4.y * b4.x; acc[5] += a4.y * b4.y; acc[6] += a4.y * b4.z; acc[7] += a4.y * b4.w;
            acc[8] += a4.z * b4.x; acc[9] += a4.z * b4.y; acc[10] += a4.z * b4.z; acc[11] += a4.z * b4.w;
            acc[12] += a4.w * b4.x; acc[13] += a4.w * b4.y; acc[14] += a4.w * b4.z; acc[15] += a4.w * b4.w;
        }
    }
#pragma unroll
    for (int r = 0; r < 4; r++) {
        int gm = m0 + mm0 + r;
        if (gm < NN) {
            float4 c4 = make_float4(acc[r * 4 + 0], acc[r * 4 + 1], acc[r * 4 + 2], acc[r * 4 + 3]);
            *(float4*)&C[(size_t)gm * ldb + n0b + n0] = c4;
        }
    }
}

// ---------------- batchnorm: column stats (2-stage, deterministic) + apply ----------------
__global__ void k_colstats(const float* __restrict__ A, int ncols, float* __restrict__ part) {
    int blk = blockIdx.x;
    int c = threadIdx.x;  // blockDim = 192
    int rows_per = (NN + NBLK_STATS - 1) / NBLK_STATS;
    int r0 = blk * rows_per;
    int r1 = min(NN, r0 + rows_per);
    float s = 0.f, s2 = 0.f;
    if (c < ncols)
        for (int r = r0; r < r1; r++) {
            float v = A[(size_t)r * ncols + c];
            s += v; s2 += v * v;
        }
    part[blk * 384 + c] = s;
    part[blk * 384 + 192 + c] = s2;
}

__global__ void k_colfin(const float* __restrict__ part, int ncols, float* __restrict__ stats) {
    int c = threadIdx.x;
    if (c >= ncols) return;
    float s = 0.f, s2 = 0.f;
    for (int b = 0; b < NBLK_STATS; b++) { s += part[b * 384 + c]; s2 += part[b * 384 + 192 + c]; }
    float m = s / (float)NN;
    float v = s2 / (float)NN - m * m;
    stats[c] = m;
    stats[192 + c] = rsqrtf(v + 1e-5f);
}

__global__ void k_bnapply(float* __restrict__ A, int ncols, const float* __restrict__ stats,
                          int dorelu) {
    size_t idx = (size_t)blockIdx.x * blockDim.x + threadIdx.x;
    size_t total = (size_t)NN * ncols;
    if (idx >= total) return;
    int c = (int)(idx % ncols);
    float v = (A[idx] - stats[c]) * stats[192 + c];
    if (dorelu) v = fmaxf(v, 0.f);
    A[idx] = v;
}

// ---------------- edge aggregation: one warp per node ----------------
__global__ void k_agg(const float* __restrict__ h, int ldh, const int* __restrict__ rowptr,
                      const int* __restrict__ srcs, const float* __restrict__ ew,
                      float* __restrict__ osum, float* __restrict__ onrm) {
    int warp = (blockIdx.x * blockDim.x + threadIdx.x) >> 5;
    if (warp >= NN) return;
    int lane = threadIdx.x & 31;
    int r0 = rowptr[warp], r1 = rowptr[warp + 1];
    float2 s = make_float2(0.f, 0.f), nrm = make_float2(0.f, 0.f);
    for (int p = r0; p < r1; p++) {
        int si = srcs[p];
        float w = ew[p];
        float2 v = *(const float2*)&h[(size_t)si * ldh + lane * 2];
        s.x += v.x; s.y += v.y;
        nrm.x += w * v.x; nrm.y += w * v.y;
    }
    *(float2*)&osum[(size_t)warp * 64 + lane * 2] = s;
    *(float2*)&onrm[(size_t)warp * 64 + lane * 2] = nrm;
}

// ---------------- fused mixed-op slot kernel (7 GEMM panels, prebaked weights) ----------------
__global__ __launch_bounds__(256) void k_slot(const float* __restrict__ h, int ldh,
                                              const float* __restrict__ ssum,
                                              const float* __restrict__ snrm,
                                              const float* __restrict__ x0,
                                              const float* __restrict__ invdeg,
                                              const float* __restrict__ Wslot,
                                              const float* __restrict__ wvp,
                                              float* __restrict__ outp, int ldo, int addf) {
    extern __shared__ float sm[];
    float* Ah = sm;
    float* Amean = sm + TSTR;
    float* Ahs = sm + 2 * TSTR;
    float* Anorm = sm + 3 * TSTR;
    float* Agmix = sm + 4 * TSTR;
    float* Bs = sm + 5 * TSTR;
    const int tid = threadIdx.x;
    const int m0 = blockIdx.x * 64;

#pragma unroll
    for (int i = 0; i < 16; i++) {
        int idx = tid + i * 256;
        int m = idx >> 6, k = idx & 63;
        int gm = m0 + m;
        float hv = 0.f, sv = 0.f, nv = 0.f, xv = 0.f, idg = 0.f;
        if (gm < NN) {
            hv = h[(size_t)gm * ldh + k];
            sv = ssum[(size_t)gm * 64 + k];
            nv = snrm[(size_t)gm * 64 + k];
            xv = x0[(size_t)gm * 64 + k];
            idg = invdeg[gm];
        }
        Ah[k * 68 + m] = hv;
        Amean[k * 68 + m] = sv * idg;
        Ahs[k * 68 + m] = hv + sv;
        Anorm[k * 68 + m] = nv;
        Agmix[k * 68 + m] = 0.9f * nv + 0.1f * xv;
    }
    __syncthreads();

    const int tx = tid & 15, ty = tid >> 4;
    const int n0 = tx * 4, mm0 = ty * 4;
    float outv[16];
    const float wv1 = wvp[1];
    if (addf) {
#pragma unroll
        for (int r = 0; r < 4; r++) {
            int gm = m0 + mm0 + r;
            float4 c4 = (gm < NN) ? *(const float4*)&outp[(size_t)gm * ldo + n0]
                                  : make_float4(0.f, 0.f, 0.f, 0.f);
            outv[r * 4 + 0] = c4.x; outv[r * 4 + 1] = c4.y;
            outv[r * 4 + 2] = c4.z; outv[r * 4 + 3] = c4.w;
        }
    } else {
#pragma unroll
        for (int i = 0; i < 16; i++) outv[i] = 0.f;
    }
#pragma unroll
    for (int r = 0; r < 4; r++)
#pragma unroll
        for (int c = 0; c < 4; c++)
            outv[r * 4 + c] += wv1 * Ah[(n0 + c) * 68 + (mm0 + r)];

    const float* bases[5] = {Ah, Amean, Ahs, Anorm, Agmix};
    const int psrc[7] = {0, 1, 2, 3, 2, 0, 4};
    const int prelu[7] = {0, 0, 0, 1, 1, 1, 1};
    for (int p = 0; p < 7; p++) {
        __syncthreads();
#pragma unroll
        for (int i = 0; i < 16; i++) {
            int idx = tid + i * 256;
            Bs[(idx >> 6) * 68 + (idx & 63)] = Wslot[p * 4096 + idx];
        }
        __syncthreads();
        const float* As = bases[psrc[p]];
        float acc[16];
#pragma unroll
        for (int i = 0; i < 16; i++) acc[i] = 0.f;
#pragma unroll 16
        for (int k = 0; k < 64; k++) {
            float4 a4 = *(const float4*)&As[k * 68 + mm0];
            float4 b4 = *(const float4*)&Bs[k * 68 + n0];
            acc[0] += a4.x * b4.x; acc[1] += a4.x * b4.y; acc[2] += a4.x * b4.z; acc[3] += a4.x * b4.w;
            acc[4] += a4.y * b4.x; acc[5] += a4.y * b4.y; acc[6] += a4.y * b4.z; acc[7] += a4.y * b4.w;
            acc[8] += a4.z * b4.x; acc[9] += a4.z * b4.y; acc[10] += a4.z * b4.z; acc[11] += a4.z * b4.w;
            acc[12] += a4.w * b4.x; acc[13] += a4.w * b4.y; acc[14] += a4.w * b4.z; acc[15] += a4.w * b4.w;
        }
        if (prelu[p]) {
#pragma unroll
            for (int i = 0; i < 16; i++) outv[i] += fmaxf(acc[i], 0.f);
        } else {
#pragma unroll
            for (int i = 0; i < 16; i++) outv[i] += acc[i];
        }
    }
#pragma unroll
    for (int r = 0; r < 4; r++) {
        int gm = m0 + mm0 + r;
        if (gm < NN) {
            float4 c4 = make_float4(outv[r * 4 + 0], outv[r * 4 + 1], outv[r * 4 + 2], outv[r * 4 + 3]);
            *(float4*)&outp[(size_t)gm * ldo + n0] = c4;
        }
    }
}

// ---------------- classifier ----------------
__global__ void k_cls(const float* __restrict__ s1, const float* __restrict__ W,
                      const float* __restrict__ b, float* __restrict__ out) {
    int n = blockIdx.x;
    __shared__ float row[256];
    __shared__ float red[64];
    int tid = threadIdx.x;  // 64 threads
    float ls = 0.f;
#pragma unroll
    for (int i = 0; i < 4; i++) {
        float v = s1[(size_t)n * 256 + tid + i * 64];
        row[tid + i * 64] = v;
        ls += v;
    }
    red[tid] = ls;
    __syncthreads();
    for (int off = 32; off > 0; off >>= 1) {
        if (tid < off) red[tid] += red[tid + off];
        __syncthreads();
    }
    float pooled = red[0] * (1.0f / 256.0f);
    if (tid < 40) {
        float acc = b[tid] + pooled * W[tid];
#pragma unroll 8
        for (int k = 0; k < 256; k++) acc += row[k] * W[(1 + k) * 40 + tid];
        out[(size_t)n * 40 + tid] = acc;
    }
}

// ---------------- host orchestration ----------------
static void bnrun(float* buf, int ncols, int dorelu, float* part, float* stats) {
    k_colstats<<<NBLK_STATS, 192>>>(buf, ncols, part);
    k_colfin<<<1, 192>>>(part, ncols, stats);
    size_t total = (size_t)NN * ncols;
    k_bnapply<<<(int)((total + 255) / 256), 256>>>(buf, ncols, stats, dorelu);
}

extern "C" void kernel_launch(void* const* d_in, const int* in_sizes, int n_in,
                              void* d_out, int out_size) {
    const float* x = (const float*)d_in[0];
    const int* ei = (const int*)d_in[1];
    const float* alphas = (const float*)d_in[2];
    const float* stemW = (const float*)d_in[3];
    const float* preW = (const float*)d_in[4];
    const float* p0W0 = (const float*)d_in[5];
    const float* p1W0 = (const float*)d_in[6];
    const float* p0W1 = (const float*)d_in[7];
    const float* p1W1 = (const float*)d_in[8];
    const float* Wgcn = (const float*)d_in[9];
    const float* Wss = (const float*)d_in[10];
    const float* Wsn = (const float*)d_in[11];
    const float* Wgin = (const float*)d_in[12];
    const float* Wgc1 = (const float*)d_in[13];
    const float* Wgc2 = (const float*)d_in[14];
    const float* Wmlp = (const float*)d_in[15];
    const float* Wgcnii = (const float*)d_in[16];
    const float* clsW = (const float*)d_in[17];
    const float* clsb = (const float*)d_in[18];
    float* out = (float*)d_out;
    const int* srcI = ei;
    const int* dstI = ei + EE;

    float *stem, *x0p, *ap, *bp, *c0, *c1, *sums, *nrms, *wcat, *wmix, *stats, *part;
    float *invdeg, *invsqrt, *ew;
    int *deg, *cursor, *rowptr, *eid, *srcs;
    cudaGetSymbolAddress((void**)&stem, g_stem);
    cudaGetSymbolAddress((void**)&x0p, g_x0);
    cudaGetSymbolAddress((void**)&ap, g_a);
    cudaGetSymbolAddress((void**)&bp, g_b);
    cudaGetSymbolAddress((void**)&c0, g_cell0);
    cudaGetSymbolAddress((void**)&c1, g_cell1);
    cudaGetSymbolAddress((void**)&sums, g_sum);
    cudaGetSymbolAddress((void**)&nrms, g_nrm);
    cudaGetSymbolAddress((void**)&wcat, g_wcat);
    cudaGetSymbolAddress((void**)&wmix, g_wmix);
    cudaGetSymbolAddress((void**)&stats, g_stats);
    cudaGetSymbolAddress((void**)&part, g_part);
    cudaGetSymbolAddress((void**)&invdeg, g_invdeg);
    cudaGetSymbolAddress((void**)&invsqrt, g_invsqrt);
    cudaGetSymbolAddress((void**)&ew, g_ew);
    cudaGetSymbolAddress((void**)&deg, g_deg);
    cudaGetSymbolAddress((void**)&cursor, g_cursor);
    cudaGetSymbolAddress((void**)&rowptr, g_rowptr);
    cudaGetSymbolAddress((void**)&eid, g_eid);
    cudaGetSymbolAddress((void**)&srcs, g_srcs);

    cudaFuncSetAttribute(k_slot, cudaFuncAttributeMaxDynamicSharedMemorySize, SLOT_SMEM);

    // --- CSR build (deterministic via per-node eid sort) ---
    k_zero2<<<(NN + 255) / 256, 256>>>(deg, cursor);
    k_deg<<<(EE + 255) / 256, 256>>>(dstI, deg);
    k_degfin<<<(NN + 255) / 256, 256>>>(deg, invdeg, invsqrt);
    k_scan<<<1, 1024>>>(deg, rowptr);
    k_scatter<<<(EE + 255) / 256, 256>>>(dstI, rowptr, cursor, eid);
    k_sortfill<<<(NN + 127) / 128, 128>>>(rowptr, eid, srcI, invsqrt, srcs, ew);

    // --- architecture weights ---
    k_softmax<<<1, 16>>>(alphas, wmix);
    k_bake<<<28, 256>>>(wmix, Wgcn, Wss, Wsn, Wgin, Wgc1, Wgc2, Wmlp, Wgcnii, wcat);

    // --- stem + preprocess ---
    k_gemm<<<dim3(MT64, 3), 256>>>(x, 128, stemW, 192, stem, 128);
    bnrun(stem, 192, 0, part, stats);
    k_gemm<<<dim3(MT64, 1), 256>>>(x, 128, preW, 64, x0p, 128);
    bnrun(x0p, 64, 1, part, stats);

    const int aggBlocks = (NN * 32 + 255) / 256;

    // --- cells ---
    for (int ci = 0; ci < 2; ci++) {
        const float* s0 = stem; int k0 = 192;
        const float* s1 = (ci == 0) ? stem : c0;
        int k1 = (ci == 0) ? 192 : 256;
        const float* pW0 = (ci == 0) ? p0W0 : p0W1;
        const float* pW1 = (ci == 0) ? p1W0 : p1W1;
        float* cell = (ci == 0) ? c0 : c1;

        k_gemm<<<dim3(MT64, 1), 256>>>(s0, k0, pW0, 64, ap, k0);
        bnrun(ap, 64, 1, part, stats);
        k_gemm<<<dim3(MT64, 1), 256>>>(s1, k1, pW1, 64, bp, k1);
        bnrun(bp, 64, 1, part, stats);

        const float* sp[5] = {ap, bp, cell, cell + 64, cell + 128};
        const int sl[5] = {64, 64, 256, 256, 256};

        k_agg<<<aggBlocks, 256>>>(sp[0], sl[0], rowptr, srcs, ew, sums + 0 * (size_t)NSZ, nrms + 0 * (size_t)NSZ);
        k_agg<<<aggBlocks, 256>>>(sp[1], sl[1], rowptr, srcs, ew, sums + 1 * (size_t)NSZ, nrms + 1 * (size_t)NSZ);

        int ej = 0;
        for (int t = 0; t < 4; t++) {
            float* outp = cell + t * 64;
            for (int j = 0; j < t + 2; j++, ej++) {
                k_slot<<<MT64, 256, SLOT_SMEM>>>(
                    sp[j], sl[j], sums + (size_t)j * NSZ, nrms + (size_t)j * NSZ, x0p, invdeg,
                    wcat + (size_t)(ci * 14 + ej) * 7 * 4096, wmix + ej * 8, outp, 256, (j > 0) ? 1 : 0);
            }
            if (t < 3) {
                int ns = t + 2;
                k_agg<<<aggBlocks, 256>>>(sp[ns], sl[ns], rowptr, srcs, ew,
                                          sums + (size_t)ns * NSZ, nrms + (size_t)ns * NSZ);
            }
        }
    }

    // --- classifier ---
    k_cls<<<NN, 64>>>(c1, clsW, clsb, out);
}

// round 3
// speedup vs baseline: 1.0279x; 1.0279x over previous
#include <cuda_runtime.h>
#include <cuda_bf16.h>
#include <math.h>

#define NN 50000
#define EE 800000
#define MT64 ((NN + 63) / 64)
#define NSZ (NN * 64)
#define NBLK_STATS 200
#define SCAN_B ((NN + 127) / 128)
#define TS 4352              // 64*68 floats per smem tile
#define STEP_SMEM (6 * TS * 4)

// ---------------- device scratch (no runtime allocation) ----------------
__device__ float g_stem[(size_t)NN * 192];
__device__ float g_x0[(size_t)NN * 64];
__device__ float g_a[(size_t)NN * 64];
__device__ float g_b[(size_t)NN * 64];
__device__ float g_cell0[(size_t)NN * 256];
__device__ float g_cell1[(size_t)NN * 256];
__device__ float g_sum[(size_t)5 * NSZ];
__device__ float g_nrm[(size_t)5 * NSZ];
__device__ float g_wcat[28 * 7 * 4096];
__device__ float g_wmix[14 * 8];
__device__ float g_stats[384];
__device__ float g_part[NBLK_STATS * 384];
__device__ float g_invdeg[NN];
__device__ float g_invsqrt[NN];
__device__ float g_ew[EE];
__device__ int g_deg[NN];
__device__ int g_cursor[NN];
__device__ int g_rowptr[NN + 1];
__device__ int g_eid[EE];
__device__ int g_srcs[EE];
__device__ int g_bsum[512];

// ---------------- CSR construction ----------------
__global__ void k_zero2(int* a, int* b) {
    int i = blockIdx.x * blockDim.x + threadIdx.x;
    if (i < NN) { a[i] = 0; b[i] = 0; }
}

__global__ void k_deg(const int* __restrict__ dst, int* __restrict__ deg) {
    int e = blockIdx.x * blockDim.x + threadIdx.x;
    if (e < EE) atomicAdd(&deg[dst[e]], 1);
}

__global__ void k_degfin(const int* __restrict__ deg, float* __restrict__ invdeg,
                         float* __restrict__ invsqrt) {
    int i = blockIdx.x * blockDim.x + threadIdx.x;
    if (i < NN) {
        float d = (float)max(deg[i], 1);
        invdeg[i] = 1.0f / d;
        invsqrt[i] = rsqrtf(d);
    }
}

// 3-phase parallel exclusive scan of deg -> rowptr
__global__ void k_scan1(const int* __restrict__ deg, int* __restrict__ rowptr,
                        int* __restrict__ bsum) {
    __shared__ int s[128];
    int b = blockIdx.x, t = threadIdx.x;
    int i = b * 128 + t;
    int v = (i < NN) ? deg[i] : 0;
    s[t] = v;
    __syncthreads();
    for (int off = 1; off < 128; off <<= 1) {
        int u = (t >= off) ? s[t - off] : 0;
        __syncthreads();
        s[t] += u;
        __syncthreads();
    }
    if (i < NN) rowptr[i] = s[t] - v;
    if (t == 127) bsum[b] = s[127];
}

__global__ void k_scan2(int* __restrict__ bsum) {
    __shared__ int s[512];
    int t = threadIdx.x;
    int v = (t < SCAN_B) ? bsum[t] : 0;
    s[t] = v;
    __syncthreads();
    for (int off = 1; off < 512; off <<= 1) {
        int u = (t >= off) ? s[t - off] : 0;
        __syncthreads();
        s[t] += u;
        __syncthreads();
    }
    if (t < SCAN_B) bsum[t] = s[t] - v;  // exclusive block offsets
}

__global__ void k_scan3(int* __restrict__ rowptr, const int* __restrict__ bsum) {
    int i = blockIdx.x * blockDim.x + threadIdx.x;
    if (i < NN) rowptr[i] += bsum[i >> 7];
    if (i == 0) rowptr[NN] = EE;
}

__global__ void k_scatter(const int* __restrict__ dst, const int* __restrict__ rowptr,
                          int* __restrict__ cursor, int* __restrict__ eid) {
    int e = blockIdx.x * blockDim.x + threadIdx.x;
    if (e < EE) {
        int d = dst[e];
        int pos = rowptr[d] + atomicAdd(&cursor[d], 1);
        eid[pos] = e;
    }
}

__global__ void k_sortfill(const int* __restrict__ rowptr, int* __restrict__ eid,
                           const int* __restrict__ src, const float* __restrict__ invsqrt,
                           int* __restrict__ srcs, float* __restrict__ ew) {
    int n = blockIdx.x * blockDim.x + threadIdx.x;
    if (n >= NN) return;
    int r0 = rowptr[n], r1 = rowptr[n + 1];
    for (int i = r0 + 1; i < r1; i++) {  // insertion sort by edge id -> determinism
        int key = eid[i];
        int j = i - 1;
        while (j >= r0 && eid[j] > key) { eid[j + 1] = eid[j]; j--; }
        eid[j + 1] = key;
    }
    float isd = invsqrt[n];
    for (int p = r0; p < r1; p++) {
        int e = eid[p];
        int s = src[e];
        srcs[p] = s;
        ew[p] = invsqrt[s] * isd;
    }
}

// ---------------- softmax + weight baking ----------------
__global__ void k_softmax(const float* __restrict__ alphas, float* __restrict__ wmix) {
    int r = threadIdx.x;
    if (r >= 14) return;
    float m = -1e30f;
    for (int o = 0; o < 8; o++) m = fmaxf(m, alphas[r * 8 + o]);
    float e[8], s = 0.f;
    for (int o = 0; o < 8; o++) { e[o] = expf(alphas[r * 8 + o] - m); s += e[o]; }
    float inv = 1.0f / s;
    for (int o = 0; o < 8; o++) wmix[r * 8 + o] = e[o] * inv;
}

__global__ void k_bake(const float* __restrict__ wmix,
                       const float* __restrict__ Wgcn, const float* __restrict__ Wss,
                       const float* __restrict__ Wsn, const float* __restrict__ Wgin,
                       const float* __restrict__ Wgc1, const float* __restrict__ Wgc2,
                       const float* __restrict__ Wmlp, const float* __restrict__ Wgcnii,
                       float* __restrict__ wcat) {
    int s = blockIdx.x;          // 0..27  (ci*14+ej)
    int ej = s % 14;
    const float* wv = wmix + ej * 8;
    size_t o = (size_t)s * 4096;
    size_t ob = (size_t)s * 7 * 4096;
    float w1 = wv[1], w2 = wv[2], w3 = wv[3], w4 = wv[4], w5 = wv[5], w6 = wv[6], w7 = wv[7];
    for (int idx = threadIdx.x; idx < 4096; idx += blockDim.x) {
        int kk = idx >> 6, nn = idx & 63;
        // panel0 (A=h, linear): wv3*Wss + wv5*(Wgc1-Wgc2) + wv1*I (skip_connect folded in)
        float p0 = w3 * Wss[o + idx] + w5 * (Wgc1[o + idx] - Wgc2[o + idx]);
        if (kk == nn) p0 += w1;
        wcat[ob + 0 * 4096 + idx] = p0;
        // panel1 (A=s_mean, linear): wv3*Wsn
        wcat[ob + 1 * 4096 + idx] = w3 * Wsn[o + idx];
        // panel2 (A=h+s_sum, linear): wv5*Wgc2
        wcat[ob + 2 * 4096 + idx] = w5 * Wgc2[o + idx];
        // panel3 (A=s_norm, relu): wv2*Wgcn
        wcat[ob + 3 * 4096 + idx] = w2 * Wgcn[o + idx];
        // panel4 (A=h+s_sum, relu): wv4*Wgin
        wcat[ob + 4 * 4096 + idx] = w4 * Wgin[o + idx];
        // panel5 (A=h, relu): wv6*Wmlp
        wcat[ob + 5 * 4096 + idx] = w6 * Wmlp[o + idx];
        // panel6 (A=0.9*s_norm+0.1*x0, relu): wv7*Wgcnii
        wcat[ob + 6 * 4096 + idx] = w7 * Wgcnii[o + idx];
    }
}

// ---------------- generic tiled GEMM (pre/stem): C[M,Nout] = A[M,K]@B[K,Nout] ----------------
__global__ __launch_bounds__(256) void k_gemm(const float* __restrict__ A, int lda,
                                              const float* __restrict__ B, int ldb,
                                              float* __restrict__ C, int K) {
    __shared__ float As[TS];
    __shared__ float Bs[TS];
    const int tid = threadIdx.x;
    const int m0 = blockIdx.x * 64;
    const int n0b = blockIdx.y * 64;
    const int tx = tid & 15, ty = tid >> 4;
    const int n0 = tx * 4, mm0 = ty * 4;
    float acc[16];
#pragma unroll
    for (int i = 0; i < 16; i++) acc[i] = 0.f;
    for (int kt = 0; kt < K; kt += 64) {
        __syncthreads();
#pragma unroll
        for (int i = 0; i < 16; i++) {
            int idx = tid + i * 256;
            int m = idx >> 6, k = idx & 63;
            int gm = m0 + m;
            As[k * 68 + m] = (gm < NN) ? A[(size_t)gm * lda + kt + k] : 0.f;
            Bs[(idx >> 6) * 68 + (idx & 63)] = B[(size_t)(kt + (idx >> 6)) * ldb + n0b + (idx & 63)];
        }
        __syncthreads();
#pragma unroll 16
        for (int k = 0; k < 64; k++) {
            float4 a4 = *(const float4*)&As[k * 68 + mm0];
            float4 b4 = *(const float4*)&Bs[k * 68 + n0];
            acc[0] += a4.x * b4.x; acc[1] += a4.x * b4.y; acc[2] += a4.x * b4.z; acc[3] += a4.x * b4.w;
            acc[4] += a4.y * b4.x; acc[5] += a4.y * b4.y; acc[6] += a4.y * b4.z; acc[7] += a4.y * b4.w;
            acc[8] += a4.z * b4.x; acc[9] += a4.z * b4.y; acc[10] += a4.z * b4.z; acc[11] += a4.z * b4.w;
            acc[12] += a4.w * b4.x; acc[13] += a4.w * b4.y; acc[14] += a4.w * b4.z; acc[15] += a4.w * b4.w;
        }
    }
#pragma unroll
    for (int r = 0; r < 4; r++) {
        int gm = m0 + mm0 + r;
        if (gm < NN) {
            float4 c4 = make_float4(acc[r * 4 + 0], acc[r * 4 + 1], acc[r * 4 + 2], acc[r * 4 + 3]);
            *(float4*)&C[(size_t)gm * ldb + n0b + n0] = c4;
        }
    }
}

// ---------------- batchnorm ----------------
__global__ void k_colstats(const float* __restrict__ A, int ncols, float* __restrict__ part) {
    int blk = blockIdx.x;
    int c = threadIdx.x;  // 192
    int rows_per = (NN + NBLK_STATS - 1) / NBLK_STATS;
    int r0 = blk * rows_per;
    int r1 = min(NN, r0 + rows_per);
    float s = 0.f, s2 = 0.f;
    if (c < ncols)
        for (int r = r0; r < r1; r++) {
            float v = A[(size_t)r * ncols + c];
            s += v; s2 += v * v;
        }
    part[blk * 384 + c] = s;
    part[blk * 384 + 192 + c] = s2;
}

__global__ void k_colfin(const float* __restrict__ part, int ncols, float* __restrict__ stats) {
    int c = threadIdx.x;
    if (c >= ncols) return;
    float s = 0.f, s2 = 0.f;
    for (int b = 0; b < NBLK_STATS; b++) { s += part[b * 384 + c]; s2 += part[b * 384 + 192 + c]; }
    float m = s / (float)NN;
    float v = s2 / (float)NN - m * m;
    stats[c] = m;
    stats[192 + c] = rsqrtf(v + 1e-5f);
}

__global__ void k_bnapply(float* __restrict__ A, int ncols, const float* __restrict__ stats,
                          int dorelu) {
    size_t idx = (size_t)blockIdx.x * blockDim.x + threadIdx.x;
    size_t total = (size_t)NN * ncols;
    if (idx >= total) return;
    int c = (int)(idx % ncols);
    float v = (A[idx] - stats[c]) * stats[192 + c];
    if (dorelu) v = fmaxf(v, 0.f);
    A[idx] = v;
}

// ---------------- edge aggregation: one warp per node ----------------
__global__ void k_agg(const float* __restrict__ h, int ldh, const int* __restrict__ rowptr,
                      const int* __restrict__ srcs, const float* __restrict__ ew,
                      float* __restrict__ osum, float* __restrict__ onrm) {
    int warp = (blockIdx.x * blockDim.x + threadIdx.x) >> 5;
    if (warp >= NN) return;
    int lane = threadIdx.x & 31;
    int r0 = rowptr[warp], r1 = rowptr[warp + 1];
    float2 s = make_float2(0.f, 0.f), nrm = make_float2(0.f, 0.f);
    for (int p = r0; p < r1; p++) {
        int si = srcs[p];
        float w = ew[p];
        float2 v = *(const float2*)&h[(size_t)si * ldh + lane * 2];
        s.x += v.x; s.y += v.y;
        nrm.x += w * v.x; nrm.y += w * v.y;
    }
    *(float2*)&osum[(size_t)warp * 64 + lane * 2] = s;
    *(float2*)&onrm[(size_t)warp * 64 + lane * 2] = nrm;
}

// ---------------- fused step kernel: all slots of one step, 8x4 microtile ----------------
__constant__ int c_psrc[7]  = {0, 1, 2, 3, 2, 0, 4};
__constant__ int c_prelu[7] = {0, 0, 0, 1, 1, 1, 1};

__global__ __launch_bounds__(128, 2) void k_step(
    const float* __restrict__ h0, const float* __restrict__ h1, const float* __restrict__ h2,
    const float* __restrict__ h3, const float* __restrict__ h4,
    int l0, int l1, int l2, int l3, int l4,
    const float* __restrict__ sums, const float* __restrict__ nrms,
    const float* __restrict__ x0, const float* __restrict__ invdeg,
    const float* __restrict__ wbase, int nst, float* __restrict__ outp) {
    extern __shared__ float sm[];
    float* Bs = sm + 5 * TS;
    const int tid = threadIdx.x;
    const int m0 = blockIdx.x * 64;
    const int tx = tid & 15, ty = tid >> 4;
    const int n0 = tx * 4, mm0 = ty * 8;

    float outv[32];
#pragma unroll
    for (int i = 0; i < 32; i++) outv[i] = 0.f;

    // prefetch B panel 0 of slot 0
    float4 Breg[8];
    {
        const float4* W4 = (const float4*)wbase;
#pragma unroll
        for (int i = 0; i < 8; i++) Breg[i] = W4[i * 128 + tid];
    }

    for (int j = 0; j < nst; j++) {
        const float* h = (j == 0) ? h0 : (j == 1) ? h1 : (j == 2) ? h2 : (j == 3) ? h3 : h4;
        int ldh = (j == 0) ? l0 : (j == 1) ? l1 : (j == 2) ? l2 : (j == 3) ? l3 : l4;
        const float* ssum = sums + (size_t)j * NSZ;
        const float* snrm = nrms + (size_t)j * NSZ;
        const float* Wslot = wbase + (size_t)j * 7 * 4096;

        __syncthreads();  // previous slot's panels done reading A
        // build 5 A tiles in [k][m] layout, stride 68
#pragma unroll
        for (int i = 0; i < 32; i++) {
            int idx = tid + i * 128;
            int m = idx >> 6, k = idx & 63;
            int gm = m0 + m;
            float hv = 0.f, sv = 0.f, nv = 0.f, xv = 0.f, idg = 0.f;
            if (gm < NN) {
                hv = h[(size_t)gm * ldh + k];
                sv = ssum[(size_t)gm * 64 + k];
                nv = snrm[(size_t)gm * 64 + k];
                xv = x0[(size_t)gm * 64 + k];
                idg = invdeg[gm];
            }
            int a = k * 68 + m;
            sm[0 * TS + a] = hv;                       // Ah
            sm[1 * TS + a] = sv * idg;                 // Amean
            sm[2 * TS + a] = hv + sv;                  // Ahs
            sm[3 * TS + a] = nv;                       // Anorm
            sm[4 * TS + a] = 0.9f * nv + 0.1f * xv;    // Agmix
        }

        for (int p = 0; p < 7; p++) {
            __syncthreads();  // Bs free (prev panel done); A ready (p==0)
            // publish prefetched B
#pragma unroll
            for (int i = 0; i < 8; i++) {
                int idx = (i * 128 + tid) * 4;
                *(float4*)&Bs[(idx >> 6) * 68 + (idx & 63)] = Breg[i];
            }
            __syncthreads();
            // prefetch next panel (or next slot's panel 0)
            const float* wp = 0;
            if (p < 6) wp = Wslot + (size_t)(p + 1) * 4096;
            else if (j + 1 < nst) wp = Wslot + (size_t)7 * 4096;
            if (wp) {
                const float4* W4 = (const float4*)wp;
#pragma unroll
                for (int i = 0; i < 8; i++) Breg[i] = W4[i * 128 + tid];
            }
            const float* As = sm + c_psrc[p] * TS;
            float acc[32];
#pragma unroll
            for (int i = 0; i < 32; i++) acc[i] = 0.f;
#pragma unroll 8
            for (int k = 0; k < 64; k++) {
                float4 a0 = *(const float4*)&As[k * 68 + mm0];
                float4 a1 = *(const float4*)&As[k * 68 + mm0 + 4];
                float4 b4 = *(const float4*)&Bs[k * 68 + n0];
                acc[0]  += a0.x * b4.x; acc[1]  += a0.x * b4.y; acc[2]  += a0.x * b4.z; acc[3]  += a0.x * b4.w;
                acc[4]  += a0.y * b4.x; acc[5]  += a0.y * b4.y; acc[6]  += a0.y * b4.z; acc[7]  += a0.y * b4.w;
                acc[8]  += a0.z * b4.x; acc[9]  += a0.z * b4.y; acc[10] += a0.z * b4.z; acc[11] += a0.z * b4.w;
                acc[12] += a0.w * b4.x; acc[13] += a0.w * b4.y; acc[14] += a0.w * b4.z; acc[15] += a0.w * b4.w;
                acc[16] += a1.x * b4.x; acc[17] += a1.x * b4.y; acc[18] += a1.x * b4.z; acc[19] += a1.x * b4.w;
                acc[20] += a1.y * b4.x; acc[21] += a1.y * b4.y; acc[22] += a1.y * b4.z; acc[23] += a1.y * b4.w;
                acc[24] += a1.z * b4.x; acc[25] += a1.z * b4.y; acc[26] += a1.z * b4.z; acc[27] += a1.z * b4.w;
                acc[28] += a1.w * b4.x; acc[29] += a1.w * b4.y; acc[30] += a1.w * b4.z; acc[31] += a1.w * b4.w;
            }
            if (c_prelu[p]) {
#pragma unroll
                for (int i = 0; i < 32; i++) outv[i] += fmaxf(acc[i], 0.f);
            } else {
#pragma unroll
                for (int i = 0; i < 32; i++) outv[i] += acc[i];
            }
        }
    }
    // single write of the new state
#pragma unroll
    for (int r = 0; r < 8; r++) {
        int gm = m0 + mm0 + r;
        if (gm < NN) {
            float4 c4 = make_float4(outv[r * 4 + 0], outv[r * 4 + 1], outv[r * 4 + 2], outv[r * 4 + 3]);
            *(float4*)&outp[(size_t)gm * 256 + n0] = c4;
        }
    }
}

// ---------------- classifier ----------------
__global__ void k_cls(const float* __restrict__ s1, const float* __restrict__ W,
                      const float* __restrict__ b, float* __restrict__ out) {
    int n = blockIdx.x;
    __shared__ float row[256];
    __shared__ float red[64];
    int tid = threadIdx.x;  // 64
    float ls = 0.f;
#pragma unroll
    for (int i = 0; i < 4; i++) {
        float v = s1[(size_t)n * 256 + tid + i * 64];
        row[tid + i * 64] = v;
        ls += v;
    }
    red[tid] = ls;
    __syncthreads();
    for (int off = 32; off > 0; off >>= 1) {
        if (tid < off) red[tid] += red[tid + off];
        __syncthreads();
    }
    float pooled = red[0] * (1.0f / 256.0f);
    if (tid < 40) {
        float acc = b[tid] + pooled * W[tid];
#pragma unroll 8
        for (int k = 0; k < 256; k++) acc += row[k] * W[(1 + k) * 40 + tid];
        out[(size_t)n * 40 + tid] = acc;
    }
}

// ---------------- host orchestration ----------------
static void bnrun(float* buf, int ncols, int dorelu, float* part, float* stats) {
    k_colstats<<<NBLK_STATS, 192>>>(buf, ncols, part);
    k_colfin<<<1, 192>>>(part, ncols, stats);
    size_t total = (size_t)NN * ncols;
    k_bnapply<<<(int)((total + 255) / 256), 256>>>(buf, ncols, stats, dorelu);
}

extern "C" void kernel_launch(void* const* d_in, const int* in_sizes, int n_in,
                              void* d_out, int out_size) {
    const float* x = (const float*)d_in[0];
    const int* ei = (const int*)d_in[1];
    const float* alphas = (const float*)d_in[2];
    const float* stemW = (const float*)d_in[3];
    const float* preW = (const float*)d_in[4];
    const float* p0W0 = (const float*)d_in[5];
    const float* p1W0 = (const float*)d_in[6];
    const float* p0W1 = (const float*)d_in[7];
    const float* p1W1 = (const float*)d_in[8];
    const float* Wgcn = (const float*)d_in[9];
    const float* Wss = (const float*)d_in[10];
    const float* Wsn = (const float*)d_in[11];
    const float* Wgin = (const float*)d_in[12];
    const float* Wgc1 = (const float*)d_in[13];
    const float* Wgc2 = (const float*)d_in[14];
    const float* Wmlp = (const float*)d_in[15];
    const float* Wgcnii = (const float*)d_in[16];
    const float* clsW = (const float*)d_in[17];
    const float* clsb = (const float*)d_in[18];
    float* out = (float*)d_out;
    const int* srcI = ei;
    const int* dstI = ei + EE;

    float *stem, *x0p, *ap, *bp, *c0, *c1, *sums, *nrms, *wcat, *wmix, *stats, *part;
    float *invdeg, *invsqrt, *ew;
    int *deg, *cursor, *rowptr, *eid, *srcs, *bsum;
    cudaGetSymbolAddress((void**)&stem, g_stem);
    cudaGetSymbolAddress((void**)&x0p, g_x0);
    cudaGetSymbolAddress((void**)&ap, g_a);
    cudaGetSymbolAddress((void**)&bp, g_b);
    cudaGetSymbolAddress((void**)&c0, g_cell0);
    cudaGetSymbolAddress((void**)&c1, g_cell1);
    cudaGetSymbolAddress((void**)&sums, g_sum);
    cudaGetSymbolAddress((void**)&nrms, g_nrm);
    cudaGetSymbolAddress((void**)&wcat, g_wcat);
    cudaGetSymbolAddress((void**)&wmix, g_wmix);
    cudaGetSymbolAddress((void**)&stats, g_stats);
    cudaGetSymbolAddress((void**)&part, g_part);
    cudaGetSymbolAddress((void**)&invdeg, g_invdeg);
    cudaGetSymbolAddress((void**)&invsqrt, g_invsqrt);
    cudaGetSymbolAddress((void**)&ew, g_ew);
    cudaGetSymbolAddress((void**)&deg, g_deg);
    cudaGetSymbolAddress((void**)&cursor, g_cursor);
    cudaGetSymbolAddress((void**)&rowptr, g_rowptr);
    cudaGetSymbolAddress((void**)&eid, g_eid);
    cudaGetSymbolAddress((void**)&srcs, g_srcs);
    cudaGetSymbolAddress((void**)&bsum, g_bsum);

    cudaFuncSetAttribute(k_step, cudaFuncAttributeMaxDynamicSharedMemorySize, STEP_SMEM);

    // --- CSR build (deterministic via per-node eid sort) ---
    k_zero2<<<(NN + 255) / 256, 256>>>(deg, cursor);
    k_deg<<<(EE + 255) / 256, 256>>>(dstI, deg);
    k_degfin<<<(NN + 255) / 256, 256>>>(deg, invdeg, invsqrt);
    k_scan1<<<SCAN_B, 128>>>(deg, rowptr, bsum);
    k_scan2<<<1, 512>>>(bsum);
    k_scan3<<<(NN + 255) / 256, 256>>>(rowptr, bsum);
    k_scatter<<<(EE + 255) / 256, 256>>>(dstI, rowptr, cursor, eid);
    k_sortfill<<<(NN + 127) / 128, 128>>>(rowptr, eid, srcI, invsqrt, srcs, ew);

    // --- architecture weights ---
    k_softmax<<<1, 16>>>(alphas, wmix);
    k_bake<<<28, 256>>>(wmix, Wgcn, Wss, Wsn, Wgin, Wgc1, Wgc2, Wmlp, Wgcnii, wcat);

    // --- stem + preprocess ---
    k_gemm<<<dim3(MT64, 3), 256>>>(x, 128, stemW, 192, stem, 128);
    bnrun(stem, 192, 0, part, stats);
    k_gemm<<<dim3(MT64, 1), 256>>>(x, 128, preW, 64, x0p, 128);
    bnrun(x0p, 64, 1, part, stats);

    const int aggBlocks = (NN * 32 + 255) / 256;

    // --- cells ---
    for (int ci = 0; ci < 2; ci++) {
        const float* s0 = stem; int k0 = 192;
        const float* s1 = (ci == 0) ? stem : c0;
        int k1 = (ci == 0) ? 192 : 256;
        const float* pW0 = (ci == 0) ? p0W0 : p0W1;
        const float* pW1 = (ci == 0) ? p1W0 : p1W1;
        float* cell = (ci == 0) ? c0 : c1;

        k_gemm<<<dim3(MT64, 1), 256>>>(s0, k0, pW0, 64, ap, k0);
        bnrun(ap, 64, 1, part, stats);
        k_gemm<<<dim3(MT64, 1), 256>>>(s1, k1, pW1, 64, bp, k1);
        bnrun(bp, 64, 1, part, stats);

        const float* sp[5] = {ap, bp, cell, cell + 64, cell + 128};
        const int sl[5] = {64, 64, 256, 256, 256};

        k_agg<<<aggBlocks, 256>>>(sp[0], sl[0], rowptr, srcs, ew, sums + 0 * (size_t)NSZ, nrms + 0 * (size_t)NSZ);
        k_agg<<<aggBlocks, 256>>>(sp[1], sl[1], rowptr, srcs, ew, sums + 1 * (size_t)NSZ, nrms + 1 * (size_t)NSZ);

        int ej0 = 0;
        for (int t = 0; t < 4; t++) {
            float* outp = cell + t * 64;
            const float* wbase = wcat + (size_t)(ci * 14 + ej0) * 7 * 4096;
            k_step<<<MT64, 128, STEP_SMEM>>>(sp[0], sp[1], sp[2], sp[3], sp[4],
                                             sl[0], sl[1], sl[2], sl[3], sl[4],
                                             sums, nrms, x0p, invdeg, wbase, t + 2, outp);
            ej0 += t + 2;
            if (t < 3) {
                int ns = t + 2;
                k_agg<<<aggBlocks, 256>>>(sp[ns], sl[ns], rowptr, srcs, ew,
                                          sums + (size_t)ns * NSZ, nrms + (size_t)ns * NSZ);
            }
        }
    }

    // --- classifier ---
    k_cls<<<NN, 64>>>(c1, clsW, clsb, out);
}